// round 15
// baseline (speedup 1.0000x reference)
#include <cuda_runtime.h>
#include <cuda_fp16.h>
#include <cstdint>

#define BN   16
#define C    256
#define H    56
#define W    56
#define OC   256
#define HW   (H*W)          // 3136
#define NPIX (BN*HW)        // 50176
#define TPB  784            // tiles per image (28*28)
#define NT   (BN*TPB)       // 12544 winograd tiles

#define X_ELEMS  (BN*C*H*W) // 12845056
#define W_ELEMS  (OC*C*3*3) // 589824
#define B_ELEMS  (OC)       // 256

// ---- device globals (allocation-free rule) ----
__device__ __half g_xh[NPIX * C];           // NHWC f16 (unscaled ints)
__device__ __half g_U[16 * NT * C];         // V = Bt d B : [xi][tile][c]
__device__ __half g_Uw[16 * OC * C];        // GgGt      : [xi][oc][c]

// output-transform coefficients: ct[xi*4+xj] = A[u][xi]*A[v][xj] for uv=00,01,10,11
__constant__ float4 c_ct[16] = {
    {1,0,0,0},{1,1,0,0},{1,-1,0,0},{0,-1,0,0},
    {1,0,1,0},{1,1,1,1},{1,-1,1,-1},{0,-1,0,-1},
    {1,0,-1,0},{1,1,-1,-1},{1,-1,-1,1},{0,-1,0,1},
    {0,0,-1,0},{0,0,-1,-1},{0,0,-1,1},{0,0,0,1}
};

// ================= pack: NCHW int32 -> NHWC f16 =================
#define XWORK (NPIX * 32)
__global__ void pack_xh_kernel(const int* __restrict__ x) {
    int idx = blockIdx.x * blockDim.x + threadIdx.x;
    int pix = idx % NPIX;
    int grp = idx / NPIX;
    int c0 = grp * 8;
    int w = pix % W;
    int t = pix / W;
    int h = t % H;
    int b = t / H;
    const int* p = x + ((b * C + c0) * H + h) * W + w;
    __align__(16) __half v[8];
    #pragma unroll
    for (int k = 0; k < 8; k++) v[k] = __float2half((float)p[k * HW]);
    *(uint4*)&g_xh[(size_t)pix * C + c0] = *(const uint4*)v;
}

// ================= weight transform: GgGt =================
__global__ void wtrans_kernel(const int* __restrict__ wsrc) {
    int id = blockIdx.x * blockDim.x + threadIdx.x;    // 65536
    int oc = id >> 8, c = id & 255;
    const int* gp = wsrc + (oc * C + c) * 9;
    float g[9];
    #pragma unroll
    for (int k = 0; k < 9; k++) g[k] = (float)gp[k];
    float Gg[4][3];
    #pragma unroll
    for (int kw = 0; kw < 3; kw++) {
        Gg[0][kw] = g[kw];
        Gg[1][kw] = 0.5f * (g[kw] + g[3 + kw] + g[6 + kw]);
        Gg[2][kw] = 0.5f * (g[kw] - g[3 + kw] + g[6 + kw]);
        Gg[3][kw] = g[6 + kw];
    }
    #pragma unroll
    for (int i = 0; i < 4; i++) {
        float u0 = Gg[i][0], u1 = Gg[i][1], u2 = Gg[i][2];
        float uw[4] = { u0, 0.5f * (u0 + u1 + u2), 0.5f * (u0 - u1 + u2), u2 };
        #pragma unroll
        for (int j = 0; j < 4; j++)
            g_Uw[(((size_t)(i * 4 + j)) * OC + oc) * C + c] = __float2half(uw[j]);
    }
}

// ================= input transform: V = Bt d B =================
struct __align__(16) H8 { __half2 h[4]; };
__device__ __forceinline__ H8 add8(H8 a, H8 b) {
    H8 r;
    #pragma unroll
    for (int k = 0; k < 4; k++) r.h[k] = __hadd2(a.h[k], b.h[k]);
    return r;
}
__device__ __forceinline__ H8 sub8(H8 a, H8 b) {
    H8 r;
    #pragma unroll
    for (int k = 0; k < 4; k++) r.h[k] = __hsub2(a.h[k], b.h[k]);
    return r;
}

__global__ void xtrans_kernel() {
    int id = blockIdx.x * blockDim.x + threadIdx.x;    // NT*32
    int c8 = id & 31;
    int t  = id >> 5;
    int b = t / TPB, rem = t % TPB;
    int th = rem / 28, tw = rem % 28;
    const __half* base = g_xh + (size_t)b * HW * C + c8 * 8;
    const int ih0 = 2 * th - 1, iw0 = 2 * tw - 1;

    H8 zero;
    #pragma unroll
    for (int k = 0; k < 4; k++) zero.h[k] = __float2half2_rn(0.0f);

    H8 tmp[4][4];
    #pragma unroll
    for (int s = 0; s < 4; s++) {
        int iw = iw0 + s;
        bool wok = (unsigned)iw < (unsigned)W;
        H8 d[4];
        #pragma unroll
        for (int r = 0; r < 4; r++) {
            int ih = ih0 + r;
            bool ok = wok && ((unsigned)ih < (unsigned)H);
            d[r] = ok ? *reinterpret_cast<const H8*>(base + ((size_t)ih * W + iw) * C)
                      : zero;
        }
        tmp[0][s] = sub8(d[0], d[2]);
        tmp[1][s] = add8(d[1], d[2]);
        tmp[2][s] = sub8(d[2], d[1]);
        tmp[3][s] = sub8(d[1], d[3]);
    }
    #pragma unroll
    for (int i = 0; i < 4; i++) {
        H8 v[4];
        v[0] = sub8(tmp[i][0], tmp[i][2]);
        v[1] = add8(tmp[i][1], tmp[i][2]);
        v[2] = sub8(tmp[i][2], tmp[i][1]);
        v[3] = sub8(tmp[i][1], tmp[i][3]);
        #pragma unroll
        for (int j = 0; j < 4; j++)
            *reinterpret_cast<H8*>(g_U + (((size_t)(i * 4 + j)) * NT + t) * C + c8 * 8) = v[j];
    }
}

// ================= fused GEMM + output transform ======================
#define MTIL  128           // tiles per block
#define NTIL  64            // oc per block
#define NTHR  512
#define KC    128           // k chunk per stage
#define NSTG  32            // 16 xi * 2 kc
#define NRING 4
#define RSTR  272           // 256B row + 16B pad
#define A_SZ  (MTIL*RSTR)   // 34816
#define B_SZ  (NTIL*RSTR)   // 17408
#define BUFSZ (A_SZ+B_SZ)   // 52224
#define SMEMB (NRING*BUFSZ) // 208896

__device__ __forceinline__ uint32_t smem_u32(const void* p) {
    uint32_t a;
    asm("{ .reg .u64 t; cvta.to.shared.u64 t, %1; cvt.u32.u64 %0, t; }" : "=r"(a) : "l"(p));
    return a;
}
__device__ __forceinline__ void mma_f16f32(float* c, const unsigned* a, const unsigned* b) {
    asm volatile(
        "mma.sync.aligned.m16n8k16.row.col.f32.f16.f16.f32 "
        "{%0,%1,%2,%3}, {%4,%5,%6,%7}, {%8,%9}, {%0,%1,%2,%3};"
        : "+f"(c[0]), "+f"(c[1]), "+f"(c[2]), "+f"(c[3])
        : "r"(a[0]), "r"(a[1]), "r"(a[2]), "r"(a[3]), "r"(b[0]), "r"(b[1]));
}
#define LDSM_X4(r0, r1, r2, r3, addr)                                        \
    asm volatile("ldmatrix.sync.aligned.m8n8.x4.shared.b16 {%0,%1,%2,%3}, [%4];" \
        : "=r"(r0), "=r"(r1), "=r"(r2), "=r"(r3) : "r"(addr))
#define CP16(dst, src) \
    asm volatile("cp.async.cg.shared.global [%0], [%1], 16, 16;" \
                 :: "r"(dst), "l"(src))
#define CP_COMMIT() asm volatile("cp.async.commit_group;" ::: "memory")
#define CP_WAIT2()  asm volatile("cp.async.wait_group 2;" ::: "memory")

__global__ __launch_bounds__(NTHR, 1)
void wino_gemm_kernel(const int* __restrict__ bias, float* __restrict__ out) {
    extern __shared__ __align__(16) char dsm[];
    const uint32_t sbase = smem_u32(dsm);

    const int tid = threadIdx.x;
    const int lane = tid & 31;
    const int wid  = tid >> 5;       // 0..15
    const int g    = lane >> 2;
    const int tig  = lane & 3;
    const int wm   = wid & 3;        // 4 m-tiles of 32
    const int wn   = wid >> 2;       // 4 n-tiles of 16
    const int nb   = blockIdx.x * NTIL;   // x = n-block: adjacent blocks share A in L2
    const int t0   = blockIdx.y * MTIL;

    // ldmatrix offsets within a buffer (R13-verified warp-16-n mapping)
    const uint32_t aoff = (uint32_t)((wm * 32 + (lane & 15)) * RSTR + ((lane >> 4) & 1) * 16);
    const uint32_t boff = (uint32_t)(A_SZ + (wn * 16 + ((lane >> 4) & 1) * 8 + (lane & 7)) * RSTR
                                     + ((lane >> 3) & 1) * 16);

    float outAcc[2][2][4][4];   // [im][jn][p][uv] = 64 regs
    #pragma unroll
    for (int im = 0; im < 2; im++)
        #pragma unroll
        for (int jn = 0; jn < 2; jn++)
            #pragma unroll
            for (int p = 0; p < 4; p++)
                #pragma unroll
                for (int uv = 0; uv < 4; uv++) outAcc[im][jn][p][uv] = 0.0f;

    float m[2][2][4];           // 16 regs
    #pragma unroll
    for (int im = 0; im < 2; im++)
        #pragma unroll
        for (int jn = 0; jn < 2; jn++)
            #pragma unroll
            for (int p = 0; p < 4; p++) m[im][jn][p] = 0.0f;

    auto stage_copy = [&](int s, int buf) {
        const int xi = s >> 1, kc = s & 1;
        const uint32_t bo = (uint32_t)(buf * BUFSZ);
        const __half* srcA = g_U  + ((size_t)xi * NT + t0) * C + kc * KC;
        const __half* srcB = g_Uw + ((size_t)xi * OC + nb) * C + kc * KC;
        #pragma unroll
        for (int it = 0; it < 4; it++) {
            int chunk = tid + it * NTHR;     // 0..2047
            int mr = chunk >> 4, j = chunk & 15;
            CP16(sbase + bo + (uint32_t)(mr * RSTR + j * 16), srcA + (size_t)mr * C + j * 8);
        }
        #pragma unroll
        for (int it = 0; it < 2; it++) {
            int chunk = tid + it * NTHR;     // 0..1023
            int mr = chunk >> 4, j = chunk & 15;
            CP16(sbase + bo + (uint32_t)(A_SZ + mr * RSTR + j * 16), srcB + (size_t)mr * C + j * 8);
        }
    };

    // prologue: stages 0..2
    #pragma unroll
    for (int ps = 0; ps < NRING - 1; ps++) {
        stage_copy(ps, ps);
        CP_COMMIT();
    }

    for (int s = 0; s < NSTG; s++) {
        CP_WAIT2();
        __syncthreads();
        const int sp = s + NRING - 1;
        if (sp < NSTG) stage_copy(sp, sp & (NRING - 1));
        CP_COMMIT();

        const uint32_t bufo = (uint32_t)((s & (NRING - 1)) * BUFSZ);
        const uint32_t aT = sbase + bufo + aoff;
        const uint32_t bT = sbase + bufo + boff;

        #pragma unroll
        for (int kq = 0; kq < KC / 16; kq++) {
            const uint32_t kb = (uint32_t)(kq * 32);
            unsigned a[2][4];
            #pragma unroll
            for (int im = 0; im < 2; im++)
                LDSM_X4(a[im][0], a[im][1], a[im][2], a[im][3],
                        aT + kb + (uint32_t)(im * 16 * RSTR));
            unsigned bf[2][2];
            LDSM_X4(bf[0][0], bf[0][1], bf[1][0], bf[1][1], bT + kb);
            #pragma unroll
            for (int im = 0; im < 2; im++)
                #pragma unroll
                for (int jn = 0; jn < 2; jn++)
                    mma_f16f32(m[im][jn], a[im], bf[jn]);
        }

        if (s & 1) {   // second k-chunk of this xi done: fold into output accumulators
            const float4 cf = c_ct[s >> 1];
            #pragma unroll
            for (int im = 0; im < 2; im++)
                #pragma unroll
                for (int jn = 0; jn < 2; jn++)
                    #pragma unroll
                    for (int p = 0; p < 4; p++) {
                        float mv = m[im][jn][p];
                        outAcc[im][jn][p][0] += cf.x * mv;
                        outAcc[im][jn][p][1] += cf.y * mv;
                        outAcc[im][jn][p][2] += cf.z * mv;
                        outAcc[im][jn][p][3] += cf.w * mv;
                        m[im][jn][p] = 0.0f;
                    }
        }
    }

    // epilogue: y[u][v] + bias -> NCHW float
    #pragma unroll
    for (int im = 0; im < 2; im++)
        #pragma unroll
        for (int jn = 0; jn < 2; jn++)
            #pragma unroll
            for (int p = 0; p < 4; p++) {
                int r = wm * 32 + im * 16 + g + (p >> 1) * 8;
                int ocl = wn * 16 + jn * 8 + tig * 2 + (p & 1);
                int t = t0 + r;
                int b = t / TPB, rem = t % TPB;
                int th = rem / 28, tw = rem % 28;
                int oc = nb + ocl;
                float bv = (float)__ldg(&bias[oc]);
                float* yb = out + (((size_t)b * OC + oc) * H + 2 * th) * W + 2 * tw;
                const float* o = outAcc[im][jn][p];
                float2 r0 = { o[0] + bv, o[1] + bv };
                float2 r1 = { o[2] + bv, o[3] + bv };
                *(float2*)yb = r0;
                *(float2*)(yb + W) = r1;
            }
}

extern "C" void kernel_launch(void* const* d_in, const int* in_sizes, int n_in,
                              void* d_out, int out_size) {
    const int* x    = nullptr;
    const int* wsrc = nullptr;
    const int* bias = nullptr;
    for (int i = 0; i < n_in; i++) {
        if (in_sizes[i] == X_ELEMS)      x    = (const int*)d_in[i];
        else if (in_sizes[i] == W_ELEMS) wsrc = (const int*)d_in[i];
        else if (in_sizes[i] == B_ELEMS) bias = (const int*)d_in[i];
    }
    if (!x)    x    = (const int*)d_in[0];
    if (!wsrc) wsrc = (const int*)d_in[1];
    if (!bias) bias = (const int*)d_in[2];

    float* out = (float*)d_out;

    pack_xh_kernel<<<XWORK / 256, 256>>>(x);
    wtrans_kernel<<<(OC * C) / 256, 256>>>(wsrc);
    xtrans_kernel<<<(NT * 32) / 256, 256>>>();

    cudaFuncSetAttribute(wino_gemm_kernel,
                         cudaFuncAttributeMaxDynamicSharedMemorySize, SMEMB);
    dim3 grid(OC / NTIL, NT / MTIL);    // (4, 98): n fastest -> A-tile L2 reuse
    wino_gemm_kernel<<<grid, NTHR, SMEMB>>>(bias, out);
}

// round 16
// speedup vs baseline: 1.1751x; 1.1751x over previous
#include <cuda_runtime.h>
#include <cuda_fp16.h>
#include <cstdint>

#define BN   16
#define C    256
#define H    56
#define W    56
#define OC   256
#define HW   (H*W)          // 3136
#define NPIX (BN*HW)        // 50176
#define TPB  784            // tiles per image (28*28)
#define NT   (BN*TPB)       // 12544 winograd tiles

#define X_ELEMS  (BN*C*H*W) // 12845056
#define W_ELEMS  (OC*C*3*3) // 589824
#define B_ELEMS  (OC)       // 256

// ---- device globals (allocation-free rule) ----
__device__ __half g_xh[NPIX * C];           // NHWC f16 (unscaled ints)
__device__ __half g_U[16 * NT * C];         // V = Bt d B : [xi][tile][c]
__device__ __half g_Uw[16 * OC * C];        // GgGt      : [xi][oc][c]

// output-transform coefficients: ct[xi*4+xj] = A[u][xi]*A[v][xj] for uv=00,01,10,11
__constant__ float4 c_ct[16] = {
    {1,0,0,0},{1,1,0,0},{1,-1,0,0},{0,-1,0,0},
    {1,0,1,0},{1,1,1,1},{1,-1,1,-1},{0,-1,0,-1},
    {1,0,-1,0},{1,1,-1,-1},{1,-1,-1,1},{0,-1,0,1},
    {0,0,-1,0},{0,0,-1,-1},{0,0,-1,1},{0,0,0,1}
};

// ================= pack: NCHW int32 -> NHWC f16 =================
#define XWORK (NPIX * 32)
__global__ void pack_xh_kernel(const int* __restrict__ x) {
    int idx = blockIdx.x * blockDim.x + threadIdx.x;
    int pix = idx % NPIX;
    int grp = idx / NPIX;
    int c0 = grp * 8;
    int w = pix % W;
    int t = pix / W;
    int h = t % H;
    int b = t / H;
    const int* p = x + ((b * C + c0) * H + h) * W + w;
    __align__(16) __half v[8];
    #pragma unroll
    for (int k = 0; k < 8; k++) v[k] = __float2half((float)p[k * HW]);
    *(uint4*)&g_xh[(size_t)pix * C + c0] = *(const uint4*)v;
}

// ================= weight transform: GgGt =================
__global__ void wtrans_kernel(const int* __restrict__ wsrc) {
    int id = blockIdx.x * blockDim.x + threadIdx.x;    // 65536
    int oc = id >> 8, c = id & 255;
    const int* gp = wsrc + (oc * C + c) * 9;
    float g[9];
    #pragma unroll
    for (int k = 0; k < 9; k++) g[k] = (float)gp[k];
    float Gg[4][3];
    #pragma unroll
    for (int kw = 0; kw < 3; kw++) {
        Gg[0][kw] = g[kw];
        Gg[1][kw] = 0.5f * (g[kw] + g[3 + kw] + g[6 + kw]);
        Gg[2][kw] = 0.5f * (g[kw] - g[3 + kw] + g[6 + kw]);
        Gg[3][kw] = g[6 + kw];
    }
    #pragma unroll
    for (int i = 0; i < 4; i++) {
        float u0 = Gg[i][0], u1 = Gg[i][1], u2 = Gg[i][2];
        float uw[4] = { u0, 0.5f * (u0 + u1 + u2), 0.5f * (u0 - u1 + u2), u2 };
        #pragma unroll
        for (int j = 0; j < 4; j++)
            g_Uw[(((size_t)(i * 4 + j)) * OC + oc) * C + c] = __float2half(uw[j]);
    }
}

// ================= input transform: V = Bt d B =================
struct __align__(16) H8 { __half2 h[4]; };
__device__ __forceinline__ H8 add8(H8 a, H8 b) {
    H8 r;
    #pragma unroll
    for (int k = 0; k < 4; k++) r.h[k] = __hadd2(a.h[k], b.h[k]);
    return r;
}
__device__ __forceinline__ H8 sub8(H8 a, H8 b) {
    H8 r;
    #pragma unroll
    for (int k = 0; k < 4; k++) r.h[k] = __hsub2(a.h[k], b.h[k]);
    return r;
}

__global__ void xtrans_kernel() {
    int id = blockIdx.x * blockDim.x + threadIdx.x;    // NT*32
    int c8 = id & 31;
    int t  = id >> 5;
    int b = t / TPB, rem = t % TPB;
    int th = rem / 28, tw = rem % 28;
    const __half* base = g_xh + (size_t)b * HW * C + c8 * 8;
    const int ih0 = 2 * th - 1, iw0 = 2 * tw - 1;

    H8 zero;
    #pragma unroll
    for (int k = 0; k < 4; k++) zero.h[k] = __float2half2_rn(0.0f);

    H8 tmp[4][4];
    #pragma unroll
    for (int s = 0; s < 4; s++) {
        int iw = iw0 + s;
        bool wok = (unsigned)iw < (unsigned)W;
        H8 d[4];
        #pragma unroll
        for (int r = 0; r < 4; r++) {
            int ih = ih0 + r;
            bool ok = wok && ((unsigned)ih < (unsigned)H);
            d[r] = ok ? *reinterpret_cast<const H8*>(base + ((size_t)ih * W + iw) * C)
                      : zero;
        }
        tmp[0][s] = sub8(d[0], d[2]);
        tmp[1][s] = add8(d[1], d[2]);
        tmp[2][s] = sub8(d[2], d[1]);
        tmp[3][s] = sub8(d[1], d[3]);
    }
    #pragma unroll
    for (int i = 0; i < 4; i++) {
        H8 v[4];
        v[0] = sub8(tmp[i][0], tmp[i][2]);
        v[1] = add8(tmp[i][1], tmp[i][2]);
        v[2] = sub8(tmp[i][2], tmp[i][1]);
        v[3] = sub8(tmp[i][1], tmp[i][3]);
        #pragma unroll
        for (int j = 0; j < 4; j++)
            *reinterpret_cast<H8*>(g_U + (((size_t)(i * 4 + j)) * NT + t) * C + c8 * 8) = v[j];
    }
}

// ================= fused GEMM + output transform ======================
// Block 64x64, 128 threads, 2 CTAs/SM: cross-CTA overlap of copy/LDSM vs MMA.
#define MTIL  64            // tiles per block
#define NTIL  64            // oc per block
#define NTHR  128
#define KC    128           // k chunk per stage
#define NSTG  32            // 16 xi * 2 kc
#define NRING 3
#define RSTR  272           // 256B row + 16B pad
#define A_SZ  (MTIL*RSTR)   // 17408
#define B_SZ  (NTIL*RSTR)   // 17408
#define BUFSZ (A_SZ+B_SZ)   // 34816
#define SMEMB (NRING*BUFSZ) // 104448 per CTA; 2 CTAs/SM

__device__ __forceinline__ uint32_t smem_u32(const void* p) {
    uint32_t a;
    asm("{ .reg .u64 t; cvta.to.shared.u64 t, %1; cvt.u32.u64 %0, t; }" : "=r"(a) : "l"(p));
    return a;
}
__device__ __forceinline__ void mma_f16f32(float* c, const unsigned* a, const unsigned* b) {
    asm volatile(
        "mma.sync.aligned.m16n8k16.row.col.f32.f16.f16.f32 "
        "{%0,%1,%2,%3}, {%4,%5,%6,%7}, {%8,%9}, {%0,%1,%2,%3};"
        : "+f"(c[0]), "+f"(c[1]), "+f"(c[2]), "+f"(c[3])
        : "r"(a[0]), "r"(a[1]), "r"(a[2]), "r"(a[3]), "r"(b[0]), "r"(b[1]));
}
#define LDSM_X4(r0, r1, r2, r3, addr)                                        \
    asm volatile("ldmatrix.sync.aligned.m8n8.x4.shared.b16 {%0,%1,%2,%3}, [%4];" \
        : "=r"(r0), "=r"(r1), "=r"(r2), "=r"(r3) : "r"(addr))
#define CP16(dst, src) \
    asm volatile("cp.async.cg.shared.global [%0], [%1], 16, 16;" \
                 :: "r"(dst), "l"(src))
#define CP_COMMIT() asm volatile("cp.async.commit_group;" ::: "memory")
#define CP_WAIT1()  asm volatile("cp.async.wait_group 1;" ::: "memory")

__global__ __launch_bounds__(NTHR, 2)
void wino_gemm_kernel(const int* __restrict__ bias, float* __restrict__ out) {
    extern __shared__ __align__(16) char dsm[];
    const uint32_t sbase = smem_u32(dsm);

    const int tid = threadIdx.x;
    const int lane = tid & 31;
    const int wid  = tid >> 5;       // 0..3
    const int g    = lane >> 2;
    const int tig  = lane & 3;
    const int wm   = wid & 1;        // 2 m-tiles of 32
    const int wn   = wid >> 1;       // 2 n-tiles of 32
    const int nb   = blockIdx.x * NTIL;   // n fastest -> A-tile L2 reuse
    const int t0   = blockIdx.y * MTIL;

    // ldmatrix offsets within a buffer (R14-verified 32x32 mapping)
    const uint32_t aoff = (uint32_t)((wm * 32 + (lane & 15)) * RSTR + ((lane >> 4) & 1) * 16);
    const uint32_t boff = (uint32_t)(A_SZ + (wn * 32 + ((lane >> 4) & 1) * 8 + (lane & 7)) * RSTR
                                     + ((lane >> 3) & 1) * 16);

    float outAcc[2][4][4][4];   // [im][jn][p][uv] = 128 regs
    #pragma unroll
    for (int im = 0; im < 2; im++)
        #pragma unroll
        for (int jn = 0; jn < 4; jn++)
            #pragma unroll
            for (int p = 0; p < 4; p++)
                #pragma unroll
                for (int uv = 0; uv < 4; uv++) outAcc[im][jn][p][uv] = 0.0f;

    float m[2][4][4];           // 32 regs
    #pragma unroll
    for (int im = 0; im < 2; im++)
        #pragma unroll
        for (int jn = 0; jn < 4; jn++)
            #pragma unroll
            for (int p = 0; p < 4; p++) m[im][jn][p] = 0.0f;

    auto stage_copy = [&](int s, int buf) {
        const int xi = s >> 1, kc = s & 1;
        const uint32_t bo = (uint32_t)(buf * BUFSZ);
        const __half* srcA = g_U  + ((size_t)xi * NT + t0) * C + kc * KC;
        const __half* srcB = g_Uw + ((size_t)xi * OC + nb) * C + kc * KC;
        #pragma unroll
        for (int it = 0; it < 8; it++) {
            int chunk = tid + it * NTHR;     // 0..1023
            int mr = chunk >> 4, j = chunk & 15;
            CP16(sbase + bo + (uint32_t)(mr * RSTR + j * 16), srcA + (size_t)mr * C + j * 8);
        }
        #pragma unroll
        for (int it = 0; it < 8; it++) {
            int chunk = tid + it * NTHR;     // 0..1023
            int mr = chunk >> 4, j = chunk & 15;
            CP16(sbase + bo + (uint32_t)(A_SZ + mr * RSTR + j * 16), srcB + (size_t)mr * C + j * 8);
        }
    };

    // prologue: stages 0..1
    #pragma unroll
    for (int ps = 0; ps < NRING - 1; ps++) {
        stage_copy(ps, ps);
        CP_COMMIT();
    }

    int buf = 0;
    for (int s = 0; s < NSTG; s++) {
        CP_WAIT1();
        __syncthreads();
        const int sp = s + NRING - 1;
        int pbuf = buf + 2; if (pbuf >= NRING) pbuf -= NRING;
        if (sp < NSTG) stage_copy(sp, pbuf);
        CP_COMMIT();

        const uint32_t bufo = (uint32_t)(buf * BUFSZ);
        const uint32_t aT = sbase + bufo + aoff;
        const uint32_t bT = sbase + bufo + boff;

        #pragma unroll
        for (int kq = 0; kq < KC / 16; kq++) {
            const uint32_t kb = (uint32_t)(kq * 32);
            unsigned a[2][4];
            #pragma unroll
            for (int im = 0; im < 2; im++)
                LDSM_X4(a[im][0], a[im][1], a[im][2], a[im][3],
                        aT + kb + (uint32_t)(im * 16 * RSTR));
            unsigned bf[4][2];
            #pragma unroll
            for (int jp = 0; jp < 2; jp++)
                LDSM_X4(bf[2*jp][0], bf[2*jp][1], bf[2*jp+1][0], bf[2*jp+1][1],
                        bT + kb + (uint32_t)(jp * 16 * RSTR));
            #pragma unroll
            for (int im = 0; im < 2; im++)
                #pragma unroll
                for (int jn = 0; jn < 4; jn++)
                    mma_f16f32(m[im][jn], a[im], bf[jn]);
        }

        if (s & 1) {   // second k-chunk of this xi done: fold into output accumulators
            const float4 cf = c_ct[s >> 1];
            #pragma unroll
            for (int im = 0; im < 2; im++)
                #pragma unroll
                for (int jn = 0; jn < 4; jn++)
                    #pragma unroll
                    for (int p = 0; p < 4; p++) {
                        float mv = m[im][jn][p];
                        outAcc[im][jn][p][0] += cf.x * mv;
                        outAcc[im][jn][p][1] += cf.y * mv;
                        outAcc[im][jn][p][2] += cf.z * mv;
                        outAcc[im][jn][p][3] += cf.w * mv;
                        m[im][jn][p] = 0.0f;
                    }
        }
        if (++buf == NRING) buf = 0;
    }

    // epilogue: y[u][v] + bias -> NCHW float
    #pragma unroll
    for (int im = 0; im < 2; im++)
        #pragma unroll
        for (int jn = 0; jn < 4; jn++)
            #pragma unroll
            for (int p = 0; p < 4; p++) {
                int r = wm * 32 + im * 16 + g + (p >> 1) * 8;
                int ocl = wn * 32 + jn * 8 + tig * 2 + (p & 1);
                int t = t0 + r;
                int b = t / TPB, rem = t % TPB;
                int th = rem / 28, tw = rem % 28;
                int oc = nb + ocl;
                float bv = (float)__ldg(&bias[oc]);
                float* yb = out + (((size_t)b * OC + oc) * H + 2 * th) * W + 2 * tw;
                const float* o = outAcc[im][jn][p];
                float2 r0 = { o[0] + bv, o[1] + bv };
                float2 r1 = { o[2] + bv, o[3] + bv };
                *(float2*)yb = r0;
                *(float2*)(yb + W) = r1;
            }
}

extern "C" void kernel_launch(void* const* d_in, const int* in_sizes, int n_in,
                              void* d_out, int out_size) {
    const int* x    = nullptr;
    const int* wsrc = nullptr;
    const int* bias = nullptr;
    for (int i = 0; i < n_in; i++) {
        if (in_sizes[i] == X_ELEMS)      x    = (const int*)d_in[i];
        else if (in_sizes[i] == W_ELEMS) wsrc = (const int*)d_in[i];
        else if (in_sizes[i] == B_ELEMS) bias = (const int*)d_in[i];
    }
    if (!x)    x    = (const int*)d_in[0];
    if (!wsrc) wsrc = (const int*)d_in[1];
    if (!bias) bias = (const int*)d_in[2];

    float* out = (float*)d_out;

    pack_xh_kernel<<<XWORK / 256, 256>>>(x);
    wtrans_kernel<<<(OC * C) / 256, 256>>>(wsrc);
    xtrans_kernel<<<(NT * 32) / 256, 256>>>();

    cudaFuncSetAttribute(wino_gemm_kernel,
                         cudaFuncAttributeMaxDynamicSharedMemorySize, SMEMB);
    dim3 grid(OC / NTIL, NT / MTIL);    // (4, 196): n fastest -> A-tile L2 reuse
    wino_gemm_kernel<<<grid, NTHR, SMEMB>>>(bias, out);
}